// round 15
// baseline (speedup 1.0000x reference)
#include <cuda_runtime.h>
#include <cstdint>

// ---------------------------------------------------------------------------
// Playlist model:
//   12 embedding towers (3 single-lookup, 9 mean-pooled over L=100)
//   -> concat [B, 12*512] -> Dense(512) relu -> Dense(256) relu -> Dense(128)
//
// R15 structure:
//   * Small tables folded through W1 by linearity -> Y0 [B,512] (g_P 88x512).
//   * FUSED persistent kernel (ticket queue) overlaps pooling with GEMM1.
//     R15 pool item = 8 rows, one per WARP: each warp owns a private 3-slot
//     TMA ring (cp.async.bulk, 2KB rows) + 3 mbarriers; lane0 produces,
//     the warp consumes with __syncwarp only -- no block barriers in the
//     inner loop, 2 rows in flight per warp, 8 independent pipelines per
//     block. (R14's half-block ring paid mbar_wait + bar.sync per 5-row
//     group and kept only 1 group in flight -> latency-bound.)
//   * Queue: 64 copies + 64 groups of [10 pool, 7 gemm] + 448 gemm tickets:
//     all pooling lands in the first half of the queue so z-gated gemm
//     tiles never spin. Gating via per-(feature, 64-row-block) counters.
//   * Deadlock-free: tiles wait only on strictly-earlier tickets; producers
//     never wait. Fixed-order math (deterministic, bitwise = reference path).
// ---------------------------------------------------------------------------

#define NB   1024
#define NL   100
#define KBIG 3584          // 7 * 512

__device__ float g_X   [NB * KBIG];
__device__ float g_Y0  [NB * 512];
__device__ float g_P   [88 * 512];
__device__ float g_H1  [NB * 512];
__device__ float g_H2  [NB * 256];
__device__ float g_part[7 * NB * 512];     // split-K partials (7 x 1024 x 512)

__device__ int g_ticket;
__device__ int g_cnt[7][16];               // per (feature, 64-row block)

// W1 row offsets for the 7 big features in X-column order:
// name, track_can, artist_name, track_uri, track_name, album, genres
__constant__ int c_WOFF[7] = {0, 1024, 1536, 2048, 2560, 3584, 5632};

// Work queue: 64 copy items; 64 groups of [10 pool, 7 gemm]; 448 gemm.
// pool stream: 5 features x 128 items (8 rows each), f-major.
// gemm stream: 7 z x 128 tiles (64x64), z-major, mblk-major.
#define IT_COPY   64
#define N_ITEMS   (IT_COPY + 64 * 17 + 448)    // 1600

// smem layout (floats), dynamic:
//   [0 .. 12288)      warp rings: warp w at w*1536 (3 slots x 512)
//                     gemm overlays [0 .. 2176) (As 16x68 + Bs 16x68)
//   [12288 .. 13088)  staged indices (800 ints)
//   [13088 .. 13136)  24 mbarriers (u64): (w*3+s)
#define SM_FLOATS 13136

// ---------------------------------------------------------------------------
__device__ __forceinline__ unsigned smem_u32(const void* p) {
    return (unsigned)__cvta_generic_to_shared(p);
}
__device__ __forceinline__ void mbar_init(unsigned mbar, unsigned cnt) {
    asm volatile("mbarrier.init.shared.b64 [%0], %1;" :: "r"(mbar), "r"(cnt) : "memory");
}
__device__ __forceinline__ void mbar_expect_tx(unsigned mbar, unsigned bytes) {
    asm volatile("mbarrier.arrive.expect_tx.shared.b64 _, [%0], %1;"
                 :: "r"(mbar), "r"(bytes) : "memory");
}
__device__ __forceinline__ void mbar_wait(unsigned mbar, int phase) {
    asm volatile(
        "{\n\t.reg .pred P;\n"
        "W%=:\n\t"
        "mbarrier.try_wait.parity.acquire.cta.shared::cta.b64 P, [%0], %1, 0x989680;\n\t"
        "@!P bra W%=;\n\t}"
        :: "r"(mbar), "r"(phase) : "memory");
}
__device__ __forceinline__ void bulk2k(unsigned dst, const void* src, unsigned mb) {
    asm volatile(
        "cp.async.bulk.shared::cluster.global.mbarrier::complete_tx::bytes "
        "[%0], [%1], %2, [%3];"
        :: "r"(dst), "l"(src), "r"(2048), "r"(mb) : "memory");
}
__device__ __forceinline__ void f4acc(float4& a, const float4& v) {
    a.x += v.x; a.y += v.y; a.z += v.z; a.w += v.w;
}

// ---------------------------------------------------------------------------
__global__ void init_mega() {
    if (threadIdx.x == 0) g_ticket = 0;
    if (threadIdx.x < 112) ((int*)g_cnt)[threadIdx.x] = 0;
}

// ---------------------------------------------------------------------------
__global__ void precompute_P(const float* __restrict__ T_collab,
                             const float* __restrict__ T_dur,
                             const float* __restrict__ T_apop,
                             const float* __restrict__ T_afol,
                             const float* __restrict__ T_tpop,
                             const float* __restrict__ W1) {
    __shared__ float s_t[512];
    int r = blockIdx.x;
    const float* T; int row; int off;
    if (r < 4)       { T = T_collab; row = r;      off = 512;  }
    else if (r < 25) { T = T_dur;    row = r - 4;  off = 3072; }
    else if (r < 46) { T = T_apop;   row = r - 25; off = 4096; }
    else if (r < 67) { T = T_afol;   row = r - 46; off = 4608; }
    else             { T = T_tpop;   row = r - 67; off = 5120; }
    int n = threadIdx.x;                       // 512 threads
    s_t[n] = T[row * 512 + n];
    __syncthreads();
    float acc = 0.0f;
    const float* w = W1 + (size_t)off * 512 + n;
    #pragma unroll 8
    for (int k = 0; k < 512; ++k)
        acc = fmaf(s_t[k], w[(size_t)k * 512], acc);
    g_P[r * 512 + n] = acc;
}

// ---------------------------------------------------------------------------
__global__ void small_pool(const int* __restrict__ id_collab,
                           const int* __restrict__ seq_dur,
                           const int* __restrict__ seq_apop,
                           const int* __restrict__ seq_afol,
                           const int* __restrict__ seq_tpop) {
    __shared__ int cnt[21];
    const int b = blockIdx.x, t = threadIdx.x;     // 128 threads, float4 lanes
    const float4* P4 = (const float4*)g_P;

    const int idc = id_collab[b];
    float4 acc = __ldg(&P4[(size_t)idc * 128 + t]);
    float4 ab  = make_float4(0.f, 0.f, 0.f, 0.f);

    const int* seqs[4]  = {seq_dur, seq_apop, seq_afol, seq_tpop};
    const int  pbase[4] = {4, 25, 46, 67};

    for (int j = 0; j < 4; ++j) {
        if (t < 21) cnt[t] = 0;
        __syncthreads();
        if (t < NL) atomicAdd(&cnt[seqs[j][b * NL + t]], 1);
        __syncthreads();
        #pragma unroll
        for (int v = 0; v < 21; ++v) {
            int c = cnt[v];
            if (c) {
                float fc = (float)c;
                float4 p = __ldg(&P4[(size_t)(pbase[j] + v) * 128 + t]);
                ab.x = fmaf(fc, p.x, ab.x);
                ab.y = fmaf(fc, p.y, ab.y);
                ab.z = fmaf(fc, p.z, ab.z);
                ab.w = fmaf(fc, p.w, ab.w);
            }
        }
        __syncthreads();
    }
    float4 o;
    o.x = acc.x + 0.01f * ab.x;
    o.y = acc.y + 0.01f * ab.y;
    o.z = acc.z + 0.01f * ab.z;
    o.w = acc.w + 0.01f * ab.w;
    ((float4*)g_Y0)[(size_t)b * 128 + t] = o;
}

// ---------------------------------------------------------------------------
// Fused persistent pooling + GEMM1 kernel.
// ---------------------------------------------------------------------------
struct MegaArgs {
    const float* tbl[7];    // tables in X feature order
    const int*   idx[7];    // f<2: [B] ids; f>=2: [B,L] sequences
    const float* W1;
};

// one pool pipeline step for slot S of this warp's ring
#define POOL_STEP(S, PH, L)                                                   \
    {                                                                         \
        const unsigned mb = mbw + 8u * (S);                                   \
        mbar_wait(mb, PH); PH ^= 1;                                           \
        const float4* buf = (const float4*)(ring + (S) * 512);                \
        f4acc(acc0, buf[lane]);                                               \
        f4acc(acc1, buf[lane + 32]);                                          \
        f4acc(acc2, buf[lane + 64]);                                          \
        f4acc(acc3, buf[lane + 96]);                                          \
        __syncwarp();                                                         \
        const int nl = (L) + 3;                                               \
        if (prod && nl < NL) {                                                \
            mbar_expect_tx(mb, 2048);                                         \
            bulk2k(ring_u + (S) * 2048u, Tb + (size_t)sx[nl] * 512, mb);      \
        }                                                                     \
    }

__global__ void __launch_bounds__(256) mega(MegaArgs a) {
    extern __shared__ __align__(1024) float smem[];
    __shared__ int s_item;

    const int tid = threadIdx.x;
    float4* X4 = (float4*)g_X;

    // one-time mbarrier init (count=1: producer's arrive.expect_tx)
    const unsigned mb_base = smem_u32(smem + 13088);
    if (tid == 0) {
        #pragma unroll
        for (int k = 0; k < 24; ++k) mbar_init(mb_base + 8 * k, 1);
    }
    __syncthreads();

    // persistent per-slot phase cursors (uniform across warps/items)
    int php0 = 0, php1 = 0, php2 = 0;

    for (;;) {
        if (tid == 0) s_item = atomicAdd(&g_ticket, 1);
        __syncthreads();
        const int it = s_item;
        if (it >= N_ITEMS) break;   // uniform exit

        // ---- decode ----
        int kind;      // 0=copy, 1=pool, 2=gemm
        int f = 0, sub = 0, z = 0, r = 0;
        if (it < IT_COPY) { kind = 0; sub = it; }
        else {
            int t2 = it - IT_COPY;
            if (t2 < 64 * 17) {
                int g = t2 / 17, l = t2 - g * 17;
                if (l < 10) { int p = g * 10 + l; kind = 1; f = 2 + (p >> 7); sub = p & 127; }
                else        { int q = g * 7 + (l - 10); kind = 2; z = q >> 7; r = q & 127; }
            } else {
                int q = 448 + (t2 - 64 * 17);
                kind = 2; z = q >> 7; r = q & 127;
            }
        }

        if (kind == 0) {
            // ---- copy item: 16 b's x 2 single-lookup features ----
            const int b0 = sub * 16;
            const int feat = tid >> 7;           // 0 or 1
            const int col  = tid & 127;
            const float4* T = (const float4*)a.tbl[feat];
            #pragma unroll 4
            for (int k = 0; k < 16; ++k) {
                int b  = b0 + k;
                int id = a.idx[feat][b];
                X4[(size_t)b * 896 + feat * 128 + col] =
                    __ldg(&T[(size_t)id * 128 + col]);
            }
            __threadfence();
            __syncthreads();
            if (tid == 0) {
                atomicAdd(&g_cnt[0][sub >> 2], 1);
                atomicAdd(&g_cnt[1][sub >> 2], 1);
            }
        } else if (kind == 1) {
            // ---- pool item: 8 rows of feature f, one row per warp ----
            const int b0 = sub * 8;
            int* sidx = (int*)(smem + 12288);
            const int* seq = a.idx[f] + b0 * NL;
            for (int i = tid; i < 8 * NL; i += 256) sidx[i] = seq[i];
            __syncthreads();

            const int w = tid >> 5, lane = tid & 31;
            const int* sx = sidx + w * NL;           // this warp's 100 indices
            const float* Tb = a.tbl[f];
            float* ring = smem + w * 1536;           // 3 slots x 512 floats
            const unsigned ring_u = smem_u32(ring);
            const unsigned mbw = mb_base + (unsigned)(w * 3) * 8;
            const bool prod = (lane == 0);

            // prologue: rows 0,1,2 -> slots 0,1,2
            if (prod) {
                #pragma unroll
                for (int s = 0; s < 3; ++s) {
                    mbar_expect_tx(mbw + 8u * s, 2048);
                    bulk2k(ring_u + s * 2048u, Tb + (size_t)sx[s] * 512, mbw + 8u * s);
                }
            }

            float4 acc0 = make_float4(0.f, 0.f, 0.f, 0.f);
            float4 acc1 = acc0, acc2 = acc0, acc3 = acc0;

            #pragma unroll 1
            for (int g3 = 0; g3 < 34; ++g3) {        // 34*3 >= 100
                { int l = g3 * 3 + 0; if (l < NL) POOL_STEP(0, php0, l) }
                { int l = g3 * 3 + 1; if (l < NL) POOL_STEP(1, php1, l) }
                { int l = g3 * 3 + 2; if (l < NL) POOL_STEP(2, php2, l) }
            }

            {
                const size_t base = (size_t)(b0 + w) * 896 + f * 128;
                acc0.x *= 0.01f; acc0.y *= 0.01f; acc0.z *= 0.01f; acc0.w *= 0.01f;
                acc1.x *= 0.01f; acc1.y *= 0.01f; acc1.z *= 0.01f; acc1.w *= 0.01f;
                acc2.x *= 0.01f; acc2.y *= 0.01f; acc2.z *= 0.01f; acc2.w *= 0.01f;
                acc3.x *= 0.01f; acc3.y *= 0.01f; acc3.z *= 0.01f; acc3.w *= 0.01f;
                X4[base + lane]      = acc0;
                X4[base + lane + 32] = acc1;
                X4[base + lane + 64] = acc2;
                X4[base + lane + 96] = acc3;
            }
            __threadfence();
            __syncthreads();
            if (tid == 0) atomicAdd(&g_cnt[f][sub >> 3], 1);
        } else {
            // ---- gemm tile: 64x64, Kc=512 (feature z), split-K partial ----
            const int mblk = r >> 3, nblk = r & 7;
            const int tgt = (z < 2) ? 4 : 8;
            if (tid == 0) {
                while (atomicAdd(&g_cnt[z][mblk], 0) < tgt) __nanosleep(200);
                __threadfence();
            }
            __syncthreads();

            float (*As)[68] = (float(*)[68])smem;
            float (*Bs)[68] = (float(*)[68])(smem + 16 * 68);

            const int tx = tid & 15, ty = tid >> 4;
            const int m0 = mblk * 64, n0 = nblk * 64;
            const int k0 = z * 512;
            float* C = g_part + (size_t)z * NB * 512;

            const int a_m = tid >> 2;
            const int a_k = (tid & 3) << 2;
            const int b_k = tid >> 4;
            const int b_n = (tid & 15) << 2;

            const float* A = g_X;
            const float* Bm = a.W1;

            float4 ra = *(const float4*)(A + (size_t)(m0 + a_m) * KBIG + k0 + a_k);
            float4 rbv;
            {
                int kg = k0 + b_k;
                int wr = c_WOFF[kg >> 9] + (kg & 511);
                rbv = *(const float4*)(Bm + (size_t)wr * 512 + n0 + b_n);
            }

            float acc[4][4];
            #pragma unroll
            for (int i = 0; i < 4; ++i)
                #pragma unroll
                for (int j = 0; j < 4; ++j) acc[i][j] = 0.f;

            const int NT = 512 / 16;
            for (int t = 0; t < NT; ++t) {
                As[a_k + 0][a_m] = ra.x;
                As[a_k + 1][a_m] = ra.y;
                As[a_k + 2][a_m] = ra.z;
                As[a_k + 3][a_m] = ra.w;
                *(float4*)&Bs[b_k][b_n] = rbv;
                __syncthreads();

                if (t + 1 < NT) {
                    int kk0 = k0 + (t + 1) * 16;
                    ra = *(const float4*)(A + (size_t)(m0 + a_m) * KBIG + kk0 + a_k);
                    int kg = kk0 + b_k;
                    int wr = c_WOFF[kg >> 9] + (kg & 511);
                    rbv = *(const float4*)(Bm + (size_t)wr * 512 + n0 + b_n);
                }

                #pragma unroll
                for (int kk = 0; kk < 16; ++kk) {
                    float af[4], bf[4];
                    #pragma unroll
                    for (int i = 0; i < 4; ++i) af[i] = As[kk][ty * 4 + i];
                    #pragma unroll
                    for (int j = 0; j < 4; ++j) bf[j] = Bs[kk][tx * 4 + j];
                    #pragma unroll
                    for (int i = 0; i < 4; ++i)
                        #pragma unroll
                        for (int j = 0; j < 4; ++j)
                            acc[i][j] = fmaf(af[i], bf[j], acc[i][j]);
                }
                __syncthreads();
            }

            #pragma unroll
            for (int i = 0; i < 4; ++i) {
                int row = m0 + ty * 4 + i;
                #pragma unroll
                for (int j = 0; j < 4; ++j)
                    C[(size_t)row * 512 + n0 + tx * 4 + j] = acc[i][j];
            }
            __syncthreads();
        }
    }
}

// ---------------------------------------------------------------------------
// Scalar split-K tiled fp32 GEMM (layers 2-3), 256 threads. (R9-proven)
// ---------------------------------------------------------------------------
template<int BM, int BN, int TM, int TN>
__global__ void __launch_bounds__(256) gemm_split(
        const float* __restrict__ A, const float* __restrict__ Bm,
        int M, int N, int K, int Kc) {
    constexpr int BK = 16;
    constexpr int TX = BN / TN;
    constexpr int TY = BM / TM;
    static_assert(TX * TY == 256, "256 threads");
    static_assert(BN == 64, "B-tile loader assumes BN==64");

    __shared__ float As[BK][BM + 4];
    __shared__ float Bs[BK][BN + 4];

    const int tid = threadIdx.x;
    const int tx = tid % TX, ty = tid / TX;
    const int m0 = blockIdx.y * BM, n0 = blockIdx.x * BN;
    const int k0 = blockIdx.z * Kc;
    float* C = g_part + (size_t)blockIdx.z * M * N;

    const int  a_m   = tid >> 2;
    const int  a_k   = (tid & 3) << 2;
    const bool a_act = (BM * 4 >= 256) ? true : (tid < BM * 4);
    const int  b_k = tid >> 4;
    const int  b_n = (tid & 15) << 2;

    float4 ra = make_float4(0.f, 0.f, 0.f, 0.f);
    float4 rb;

    if (a_act) ra = *(const float4*)(A + (size_t)(m0 + a_m) * K + k0 + a_k);
    rb = *(const float4*)(Bm + (size_t)(k0 + b_k) * N + n0 + b_n);

    float acc[TM][TN];
    #pragma unroll
    for (int i = 0; i < TM; ++i)
        #pragma unroll
        for (int j = 0; j < TN; ++j) acc[i][j] = 0.f;

    const int NT = Kc / BK;
    for (int t = 0; t < NT; ++t) {
        if (a_act) {
            As[a_k + 0][a_m] = ra.x;
            As[a_k + 1][a_m] = ra.y;
            As[a_k + 2][a_m] = ra.z;
            As[a_k + 3][a_m] = ra.w;
        }
        *(float4*)&Bs[b_k][b_n] = rb;
        __syncthreads();

        if (t + 1 < NT) {
            int kk0 = k0 + (t + 1) * BK;
            if (a_act) ra = *(const float4*)(A + (size_t)(m0 + a_m) * K + kk0 + a_k);
            rb = *(const float4*)(Bm + (size_t)(kk0 + b_k) * N + n0 + b_n);
        }

        #pragma unroll
        for (int kk = 0; kk < BK; ++kk) {
            float af[TM], bf[TN];
            #pragma unroll
            for (int i = 0; i < TM; ++i) af[i] = As[kk][ty * TM + i];
            #pragma unroll
            for (int j = 0; j < TN; ++j) bf[j] = Bs[kk][tx * TN + j];
            #pragma unroll
            for (int i = 0; i < TM; ++i)
                #pragma unroll
                for (int j = 0; j < TN; ++j)
                    acc[i][j] = fmaf(af[i], bf[j], acc[i][j]);
        }
        __syncthreads();
    }

    #pragma unroll
    for (int i = 0; i < TM; ++i) {
        int row = m0 + ty * TM + i;
        #pragma unroll
        for (int j = 0; j < TN; ++j)
            C[(size_t)row * N + n0 + tx * TN + j] = acc[i][j];
    }
}

// ---------------------------------------------------------------------------
// out = act(sum_z part[z] + bias [+ C0]); fixed order -> deterministic.
// ---------------------------------------------------------------------------
template<int S, bool RELU, bool ADDC0>
__global__ void combine_k(const float* __restrict__ bias,
                          const float* __restrict__ C0,
                          float* __restrict__ out, int MN4, int N4) {
    int i = blockIdx.x * blockDim.x + threadIdx.x;
    if (i >= MN4) return;
    const float4* p = (const float4*)g_part;
    float4 v = __ldg(&((const float4*)bias)[i % N4]);
    #pragma unroll
    for (int s = 0; s < S; ++s) {
        float4 q = p[(size_t)s * MN4 + i];
        v.x += q.x; v.y += q.y; v.z += q.z; v.w += q.w;
    }
    if (ADDC0) {
        float4 c = ((const float4*)C0)[i];
        v.x += c.x; v.y += c.y; v.z += c.z; v.w += c.w;
    }
    if (RELU) {
        v.x = fmaxf(v.x, 0.f); v.y = fmaxf(v.y, 0.f);
        v.z = fmaxf(v.z, 0.f); v.w = fmaxf(v.w, 0.f);
    }
    ((float4*)out)[i] = v;
}

// ---------------------------------------------------------------------------
extern "C" void kernel_launch(void* const* d_in, const int* in_sizes, int n_in,
                              void* d_out, int out_size) {
    (void)in_sizes; (void)n_in; (void)out_size;

    const float* T_name        = (const float*)d_in[0];
    const float* T_collab      = (const float*)d_in[1];
    const float* T_track_can   = (const float*)d_in[2];
    const float* T_artist_name = (const float*)d_in[3];
    const float* T_track_uri   = (const float*)d_in[4];
    const float* T_track_name  = (const float*)d_in[5];
    const float* T_dur         = (const float*)d_in[6];
    const float* T_album       = (const float*)d_in[7];
    const float* T_apop        = (const float*)d_in[8];
    const float* T_afol        = (const float*)d_in[9];
    const float* T_tpop        = (const float*)d_in[10];
    const float* T_genres      = (const float*)d_in[11];
    const float* W1 = (const float*)d_in[12];
    const float* b1 = (const float*)d_in[13];
    const float* W2 = (const float*)d_in[14];
    const float* b2 = (const float*)d_in[15];
    const float* W3 = (const float*)d_in[16];
    const float* b3 = (const float*)d_in[17];
    const int* id_name         = (const int*)d_in[18];
    const int* id_collab       = (const int*)d_in[19];
    const int* id_track_can    = (const int*)d_in[20];
    const int* seq_artist_name = (const int*)d_in[21];
    const int* seq_track_uri   = (const int*)d_in[22];
    const int* seq_track_name  = (const int*)d_in[23];
    const int* seq_dur         = (const int*)d_in[24];
    const int* seq_album       = (const int*)d_in[25];
    const int* seq_apop        = (const int*)d_in[26];
    const int* seq_afol        = (const int*)d_in[27];
    const int* seq_tpop        = (const int*)d_in[28];
    const int* seq_genres      = (const int*)d_in[29];

    float *Y0, *H1, *H2;
    cudaGetSymbolAddress((void**)&Y0, g_Y0);
    cudaGetSymbolAddress((void**)&H1, g_H1);
    cudaGetSymbolAddress((void**)&H2, g_H2);

    MegaArgs ma;
    ma.tbl[0] = T_name;        ma.idx[0] = id_name;
    ma.tbl[1] = T_track_can;   ma.idx[1] = id_track_can;
    ma.tbl[2] = T_artist_name; ma.idx[2] = seq_artist_name;
    ma.tbl[3] = T_track_uri;   ma.idx[3] = seq_track_uri;
    ma.tbl[4] = T_track_name;  ma.idx[4] = seq_track_name;
    ma.tbl[5] = T_album;       ma.idx[5] = seq_album;
    ma.tbl[6] = T_genres;      ma.idx[6] = seq_genres;
    ma.W1 = W1;

    static bool s_attr_done = false;
    if (!s_attr_done) {
        cudaFuncSetAttribute(mega, cudaFuncAttributeMaxDynamicSharedMemorySize,
                             SM_FLOATS * 4);
        s_attr_done = true;
    }

    // independent small-feature fold (cheap, serial at front)
    precompute_P<<<88, 512>>>(T_collab, T_dur, T_apop, T_afol, T_tpop, W1);
    small_pool<<<NB, 128>>>(id_collab, seq_dur, seq_apop, seq_afol, seq_tpop);

    // fused pooling + GEMM1 (persistent, interleaved ticket queue)
    init_mega<<<1, 128>>>();
    mega<<<592, 256, SM_FLOATS * 4>>>(ma);

    // H1 = relu(sum_z part[z] + Y0 + b1)
    combine_k<7, true, true><<<(NB * 512 / 4 + 255) / 256, 256>>>(
        b1, Y0, H1, NB * 512 / 4, 512 / 4);

    // layer 2: [1024,512] @ W2; split-K=2 (Kc=256) -> 256 blocks
    gemm_split<32, 64, 2, 4><<<dim3(256 / 64, NB / 32, 2), 256>>>(
        H1, W2, NB, 256, 512, 256);
    combine_k<2, true, false><<<(NB * 256 / 4 + 255) / 256, 256>>>(
        b2, nullptr, H2, NB * 256 / 4, 256 / 4);

    // layer 3: [1024,256] @ W3; split-K=4 (Kc=64) -> 256 blocks
    gemm_split<32, 64, 2, 4><<<dim3(128 / 64, NB / 32, 4), 256>>>(
        H2, W3, NB, 128, 256, 64);
    combine_k<4, false, false><<<(NB * 128 / 4 + 255) / 256, 256>>>(
        b3, nullptr, (float*)d_out, NB * 128 / 4, 128 / 4);
}

// round 16
// speedup vs baseline: 1.7901x; 1.7901x over previous
#include <cuda_runtime.h>
#include <cstdint>

// ---------------------------------------------------------------------------
// Playlist model:
//   12 embedding towers (3 single-lookup, 9 mean-pooled over L=100)
//   -> concat [B, 12*512] -> Dense(512) relu -> Dense(256) relu -> Dense(128)
//
// R16 structure (base = R14, which measured 294us total / 226us mega):
//   * Small tables folded through W1 by linearity -> Y0 [B,512] (g_P 88x512).
//   * FUSED persistent kernel (ticket queue) overlaps TMA-ring pooling with
//     GEMM1. R16 changes ONLY the work decomposition:
//       - gemm tickets are K-chunked: (z, kc, mblk, nblk) = 64x64x128 tiles
//         (18us quanta instead of 72us) -> 28 split-K slabs. R14's 72us tile
//         quantum caused +-1-tile load imbalance and a >=72us tail after the
//         last feature's pools.
//       - both streams are mblk-major with a 3-mblk pool lead, interleaved
//         per-supergroup by exact Bresenham (164 P : 224 G), so tiles of a
//         64-row block start right after that block's pools complete.
//   * Pool item (unchanged from R14): half-block 2-slot TMA ring, 5-row
//     (10KB) groups, mbarrier tx-accounting, phase cursors in registers.
//   * Deadlock-free: tiles gate on per-(feature, mblk) counters fed by
//     strictly-earlier tickets; producers never wait. Fixed-order math.
// ---------------------------------------------------------------------------

#define NB   1024
#define NL   100
#define KBIG 3584          // 7 * 512

__device__ float g_X   [NB * KBIG];
__device__ float g_Y0  [NB * 512];
__device__ float g_P   [88 * 512];
__device__ float g_H1  [NB * 512];
__device__ float g_H2  [NB * 256];
__device__ float g_part[28 * NB * 512];    // split-K partials (28 x 1024 x 512)

__device__ int g_ticket;
__device__ int g_cnt[7][16];               // per (feature, 64-row block)

// W1 row offsets for the 7 big features in X-column order:
// name, track_can, artist_name, track_uri, track_name, album, genres
__constant__ int c_WOFF[7] = {0, 1024, 1536, 2048, 2560, 3584, 5632};

// ---- queue geometry -------------------------------------------------------
// P stream (per mblk): 4 copy items + 160 pool items (5f x 32 x 2 rows) = 164
// G stream (per mblk): 28 z-chunks x 8 nblk = 224 tiles (64x64x128)
// order: P(m=0..2) pure (492), 13 supergroups [P(m+3) 164 : G(m) 224] = 388
//        Bresenham-interleaved, then G(13..15) trailing (672).
#define N_ITEMS   (492 + 13 * 388 + 3 * 224)   // 6208

// ---------------------------------------------------------------------------
__device__ __forceinline__ unsigned smem_u32(const void* p) {
    return (unsigned)__cvta_generic_to_shared(p);
}
__device__ __forceinline__ void mbar_init(unsigned mbar, unsigned cnt) {
    asm volatile("mbarrier.init.shared.b64 [%0], %1;" :: "r"(mbar), "r"(cnt) : "memory");
}
__device__ __forceinline__ void mbar_expect_tx(unsigned mbar, unsigned bytes) {
    asm volatile("mbarrier.arrive.expect_tx.shared.b64 _, [%0], %1;"
                 :: "r"(mbar), "r"(bytes) : "memory");
}
__device__ __forceinline__ void mbar_wait(unsigned mbar, int phase) {
    asm volatile(
        "{\n\t.reg .pred P;\n"
        "W%=:\n\t"
        "mbarrier.try_wait.parity.acquire.cta.shared::cta.b64 P, [%0], %1, 0x989680;\n\t"
        "@!P bra W%=;\n\t}"
        :: "r"(mbar), "r"(phase) : "memory");
}
__device__ __forceinline__ void bulk2k(unsigned dst, const void* src, unsigned mb) {
    asm volatile(
        "cp.async.bulk.shared::cluster.global.mbarrier::complete_tx::bytes "
        "[%0], [%1], %2, [%3];"
        :: "r"(dst), "l"(src), "r"(2048), "r"(mb) : "memory");
}

// ---------------------------------------------------------------------------
__global__ void init_mega() {
    if (threadIdx.x == 0) g_ticket = 0;
    if (threadIdx.x < 112) ((int*)g_cnt)[threadIdx.x] = 0;
}

// ---------------------------------------------------------------------------
__global__ void precompute_P(const float* __restrict__ T_collab,
                             const float* __restrict__ T_dur,
                             const float* __restrict__ T_apop,
                             const float* __restrict__ T_afol,
                             const float* __restrict__ T_tpop,
                             const float* __restrict__ W1) {
    __shared__ float s_t[512];
    int r = blockIdx.x;
    const float* T; int row; int off;
    if (r < 4)       { T = T_collab; row = r;      off = 512;  }
    else if (r < 25) { T = T_dur;    row = r - 4;  off = 3072; }
    else if (r < 46) { T = T_apop;   row = r - 25; off = 4096; }
    else if (r < 67) { T = T_afol;   row = r - 46; off = 4608; }
    else             { T = T_tpop;   row = r - 67; off = 5120; }
    int n = threadIdx.x;                       // 512 threads
    s_t[n] = T[row * 512 + n];
    __syncthreads();
    float acc = 0.0f;
    const float* w = W1 + (size_t)off * 512 + n;
    #pragma unroll 8
    for (int k = 0; k < 512; ++k)
        acc = fmaf(s_t[k], w[(size_t)k * 512], acc);
    g_P[r * 512 + n] = acc;
}

// ---------------------------------------------------------------------------
__global__ void small_pool(const int* __restrict__ id_collab,
                           const int* __restrict__ seq_dur,
                           const int* __restrict__ seq_apop,
                           const int* __restrict__ seq_afol,
                           const int* __restrict__ seq_tpop) {
    __shared__ int cnt[21];
    const int b = blockIdx.x, t = threadIdx.x;     // 128 threads, float4 lanes
    const float4* P4 = (const float4*)g_P;

    const int idc = id_collab[b];
    float4 acc = __ldg(&P4[(size_t)idc * 128 + t]);
    float4 ab  = make_float4(0.f, 0.f, 0.f, 0.f);

    const int* seqs[4]  = {seq_dur, seq_apop, seq_afol, seq_tpop};
    const int  pbase[4] = {4, 25, 46, 67};

    for (int j = 0; j < 4; ++j) {
        if (t < 21) cnt[t] = 0;
        __syncthreads();
        if (t < NL) atomicAdd(&cnt[seqs[j][b * NL + t]], 1);
        __syncthreads();
        #pragma unroll
        for (int v = 0; v < 21; ++v) {
            int c = cnt[v];
            if (c) {
                float fc = (float)c;
                float4 p = __ldg(&P4[(size_t)(pbase[j] + v) * 128 + t]);
                ab.x = fmaf(fc, p.x, ab.x);
                ab.y = fmaf(fc, p.y, ab.y);
                ab.z = fmaf(fc, p.z, ab.z);
                ab.w = fmaf(fc, p.w, ab.w);
            }
        }
        __syncthreads();
    }
    float4 o;
    o.x = acc.x + 0.01f * ab.x;
    o.y = acc.y + 0.01f * ab.y;
    o.z = acc.z + 0.01f * ab.z;
    o.w = acc.w + 0.01f * ab.w;
    ((float4*)g_Y0)[(size_t)b * 128 + t] = o;
}

// ---------------------------------------------------------------------------
// Fused persistent pooling + GEMM1 kernel.
// smem layout (floats):
//   [0 .. 10240)      pool rings: half h at h*5120 (2 slots x 5 rows x 512)
//                     gemm overlays [0 .. 2176) (As 16x68 + Bs 16x68)
//   [10240 .. 10496)  staged indices: half h at 10240 + h*128 (ints)
//   [10496 .. 10504)  4 mbarriers (u64): index h*2+s
// ---------------------------------------------------------------------------
struct MegaArgs {
    const float* tbl[7];    // tables in X feature order
    const int*   idx[7];    // f<2: [B] ids; f>=2: [B,L] sequences
    const float* W1;
};

__global__ void __launch_bounds__(256) mega(MegaArgs a) {
    __shared__ __align__(1024) float smem[10504];
    __shared__ int s_item;

    const int tid = threadIdx.x;
    float4* X4 = (float4*)g_X;

    // one-time mbarrier init (count=1: the producer's arrive.expect_tx)
    const unsigned mb_base = smem_u32(smem + 10496);
    if (tid == 0) {
        #pragma unroll
        for (int k = 0; k < 4; ++k) mbar_init(mb_base + 8 * k, 1);
    }
    __syncthreads();

    // per-thread phase cursors for this half's 2 ring slots (10 flips each
    // per pool item -> even -> self-restoring across items)
    int ph0 = 0, ph1 = 0;

    for (;;) {
        if (tid == 0) s_item = atomicAdd(&g_ticket, 1);
        __syncthreads();
        const int it = s_item;
        if (it >= N_ITEMS) break;   // uniform exit

        // ---- decode: mblk-major P/G streams, Bresenham supergroups ----
        int kind;                   // 0=copy, 1=pool, 2=gemm
        int f = 0, sub = 0, r = 0;  // pool/copy: sub; gemm: z-chunk in zc, tile r
        int zc = 0, m = 0;
        if (it < 492) {
            m = it / 164;
            int pi = it - m * 164;
            if (pi < 4) { kind = 0; sub = m * 4 + pi; }
            else { int pp = pi - 4; kind = 1; f = 2 + pp / 32; sub = m * 32 + pp % 32; }
        } else {
            int t2 = it - 492;
            int sg = t2 / 388;
            if (sg < 13) {
                int p = t2 - sg * 388;
                int pa = (p * 164) / 388, pb = ((p + 1) * 164) / 388;
                if (pb > pa) {          // P ticket for mblk sg+3
                    m = sg + 3;
                    int pi = pa;
                    if (pi < 4) { kind = 0; sub = m * 4 + pi; }
                    else { int pp = pi - 4; kind = 1; f = 2 + pp / 32; sub = m * 32 + pp % 32; }
                } else {                // G ticket for mblk sg
                    m = sg;
                    int gi = p - pa;
                    kind = 2; zc = gi >> 3; r = gi & 7;
                }
            } else {
                int gi = t2 - 13 * 388;
                m = 13 + gi / 224; gi %= 224;
                kind = 2; zc = gi >> 3; r = gi & 7;
            }
        }

        if (kind == 0) {
            // ---- copy item: 16 b's x 2 single-lookup features ----
            const int b0 = sub * 16;
            const int feat = tid >> 7;           // 0 or 1
            const int col  = tid & 127;
            const float4* T = (const float4*)a.tbl[feat];
            #pragma unroll 4
            for (int k = 0; k < 16; ++k) {
                int b  = b0 + k;
                int id = a.idx[feat][b];
                X4[(size_t)b * 896 + feat * 128 + col] =
                    __ldg(&T[(size_t)id * 128 + col]);
            }
            __threadfence();
            __syncthreads();
            if (tid == 0) {
                atomicAdd(&g_cnt[0][sub >> 2], 1);
                atomicAdd(&g_cnt[1][sub >> 2], 1);
            }
        } else if (kind == 1) {
            // ---- pool item: 2 rows of feature f via TMA bulk ring ----
            const int b0 = sub * 2;
            int* sidx = (int*)(smem + 10240);
            const int* seq = a.idx[f] + b0 * NL;
            for (int i = tid; i < 2 * NL; i += 256)
                sidx[(i / NL) * 128 + (i % NL)] = seq[i];
            __syncthreads();

            const int h = tid >> 7, lt = tid & 127;
            const int* sx = sidx + h * 128;          // 100 indices (bcast LDS)
            const float* Tb = a.tbl[f];
            float* ring = smem + h * 5120;           // 2 slots x 5 rows x 512
            const unsigned ring_u = smem_u32(ring);
            const unsigned mb0 = mb_base + 8 * (h * 2);
            const unsigned mb1 = mb_base + 8 * (h * 2 + 1);
            const bool prod = (lt == 0);

            // prologue: issue groups 0 (slot0) and 1 (slot1)
            if (prod) {
                mbar_expect_tx(mb0, 10240);
                #pragma unroll
                for (int q = 0; q < 5; ++q)
                    bulk2k(ring_u + q * 2048u, Tb + (size_t)sx[q] * 512, mb0);
                mbar_expect_tx(mb1, 10240);
                #pragma unroll
                for (int q = 0; q < 5; ++q)
                    bulk2k(ring_u + 10240u + q * 2048u, Tb + (size_t)sx[5 + q] * 512, mb1);
            }

            float4 acc = make_float4(0.f, 0.f, 0.f, 0.f);
            for (int g = 0; g < 20; ++g) {
                const int s = g & 1;
                if (s == 0) { mbar_wait(mb0, ph0); ph0 ^= 1; }
                else        { mbar_wait(mb1, ph1); ph1 ^= 1; }
                // consume 5 rows (this thread's own 16B slices)
                const float* buf = ring + s * 2560;
                #pragma unroll
                for (int q = 0; q < 5; ++q) {
                    float4 v = *(const float4*)(buf + q * 512 + lt * 4);
                    acc.x += v.x; acc.y += v.y; acc.z += v.z; acc.w += v.w;
                }
                // half-scope barrier: all reads done before producer reuses slot
                asm volatile("bar.sync %0, %1;" :: "r"(1 + h), "r"(128) : "memory");
                if (prod && g + 2 < 20) {
                    const unsigned mb = (s == 0) ? mb0 : mb1;
                    mbar_expect_tx(mb, 10240);
                    #pragma unroll
                    for (int q = 0; q < 5; ++q)
                        bulk2k(ring_u + (unsigned)s * 10240u + q * 2048u,
                               Tb + (size_t)sx[(g + 2) * 5 + q] * 512, mb);
                }
            }
            acc.x *= 0.01f; acc.y *= 0.01f; acc.z *= 0.01f; acc.w *= 0.01f;
            X4[(size_t)(b0 + h) * 896 + f * 128 + lt] = acc;

            __threadfence();
            __syncthreads();
            if (tid == 0) atomicAdd(&g_cnt[f][sub >> 5], 1);
        } else {
            // ---- gemm tile: 64x64x128 (z-chunk zc of mblk m), partial ----
            const int z = zc >> 2, kc = zc & 3;
            const int nblk = r;
            const int tgt = (z < 2) ? 4 : 32;
            if (tid == 0) {
                while (atomicAdd(&g_cnt[z][m], 0) < tgt) __nanosleep(200);
                __threadfence();
            }
            __syncthreads();

            float (*As)[68] = (float(*)[68])smem;
            float (*Bs)[68] = (float(*)[68])(smem + 16 * 68);

            const int tx = tid & 15, ty = tid >> 4;
            const int m0 = m * 64, n0 = nblk * 64;
            const int k0 = z * 512 + kc * 128;
            float* C = g_part + (size_t)zc * NB * 512;

            const int a_m = tid >> 2;
            const int a_k = (tid & 3) << 2;
            const int b_k = tid >> 4;
            const int b_n = (tid & 15) << 2;

            const float* A = g_X;
            const float* Bm = a.W1;

            float4 ra = *(const float4*)(A + (size_t)(m0 + a_m) * KBIG + k0 + a_k);
            float4 rbv;
            {
                int kg = k0 + b_k;
                int wr = c_WOFF[kg >> 9] + (kg & 511);
                rbv = *(const float4*)(Bm + (size_t)wr * 512 + n0 + b_n);
            }

            float acc[4][4];
            #pragma unroll
            for (int i = 0; i < 4; ++i)
                #pragma unroll
                for (int j = 0; j < 4; ++j) acc[i][j] = 0.f;

            const int NT = 128 / 16;
            for (int t = 0; t < NT; ++t) {
                As[a_k + 0][a_m] = ra.x;
                As[a_k + 1][a_m] = ra.y;
                As[a_k + 2][a_m] = ra.z;
                As[a_k + 3][a_m] = ra.w;
                *(float4*)&Bs[b_k][b_n] = rbv;
                __syncthreads();

                if (t + 1 < NT) {
                    int kk0 = k0 + (t + 1) * 16;
                    ra = *(const float4*)(A + (size_t)(m0 + a_m) * KBIG + kk0 + a_k);
                    int kg = kk0 + b_k;
                    int wr = c_WOFF[kg >> 9] + (kg & 511);
                    rbv = *(const float4*)(Bm + (size_t)wr * 512 + n0 + b_n);
                }

                #pragma unroll
                for (int kk = 0; kk < 16; ++kk) {
                    float af[4], bf[4];
                    #pragma unroll
                    for (int i = 0; i < 4; ++i) af[i] = As[kk][ty * 4 + i];
                    #pragma unroll
                    for (int j = 0; j < 4; ++j) bf[j] = Bs[kk][tx * 4 + j];
                    #pragma unroll
                    for (int i = 0; i < 4; ++i)
                        #pragma unroll
                        for (int j = 0; j < 4; ++j)
                            acc[i][j] = fmaf(af[i], bf[j], acc[i][j]);
                }
                __syncthreads();
            }

            #pragma unroll
            for (int i = 0; i < 4; ++i) {
                int row = m0 + ty * 4 + i;
                #pragma unroll
                for (int j = 0; j < 4; ++j)
                    C[(size_t)row * 512 + n0 + tx * 4 + j] = acc[i][j];
            }
            __syncthreads();
        }
    }
}

// ---------------------------------------------------------------------------
// Scalar split-K tiled fp32 GEMM (layers 2-3), 256 threads. (R9-proven)
// ---------------------------------------------------------------------------
template<int BM, int BN, int TM, int TN>
__global__ void __launch_bounds__(256) gemm_split(
        const float* __restrict__ A, const float* __restrict__ Bm,
        int M, int N, int K, int Kc) {
    constexpr int BK = 16;
    constexpr int TX = BN / TN;
    constexpr int TY = BM / TM;
    static_assert(TX * TY == 256, "256 threads");
    static_assert(BN == 64, "B-tile loader assumes BN==64");

    __shared__ float As[BK][BM + 4];
    __shared__ float Bs[BK][BN + 4];

    const int tid = threadIdx.x;
    const int tx = tid % TX, ty = tid / TX;
    const int m0 = blockIdx.y * BM, n0 = blockIdx.x * BN;
    const int k0 = blockIdx.z * Kc;
    float* C = g_part + (size_t)blockIdx.z * M * N;

    const int  a_m   = tid >> 2;
    const int  a_k   = (tid & 3) << 2;
    const bool a_act = (BM * 4 >= 256) ? true : (tid < BM * 4);
    const int  b_k = tid >> 4;
    const int  b_n = (tid & 15) << 2;

    float4 ra = make_float4(0.f, 0.f, 0.f, 0.f);
    float4 rb;

    if (a_act) ra = *(const float4*)(A + (size_t)(m0 + a_m) * K + k0 + a_k);
    rb = *(const float4*)(Bm + (size_t)(k0 + b_k) * N + n0 + b_n);

    float acc[TM][TN];
    #pragma unroll
    for (int i = 0; i < TM; ++i)
        #pragma unroll
        for (int j = 0; j < TN; ++j) acc[i][j] = 0.f;

    const int NT = Kc / BK;
    for (int t = 0; t < NT; ++t) {
        if (a_act) {
            As[a_k + 0][a_m] = ra.x;
            As[a_k + 1][a_m] = ra.y;
            As[a_k + 2][a_m] = ra.z;
            As[a_k + 3][a_m] = ra.w;
        }
        *(float4*)&Bs[b_k][b_n] = rb;
        __syncthreads();

        if (t + 1 < NT) {
            int kk0 = k0 + (t + 1) * BK;
            if (a_act) ra = *(const float4*)(A + (size_t)(m0 + a_m) * K + kk0 + a_k);
            rb = *(const float4*)(Bm + (size_t)(kk0 + b_k) * N + n0 + b_n);
        }

        #pragma unroll
        for (int kk = 0; kk < BK; ++kk) {
            float af[TM], bf[TN];
            #pragma unroll
            for (int i = 0; i < TM; ++i) af[i] = As[kk][ty * TM + i];
            #pragma unroll
            for (int j = 0; j < TN; ++j) bf[j] = Bs[kk][tx * TN + j];
            #pragma unroll
            for (int i = 0; i < TM; ++i)
                #pragma unroll
                for (int j = 0; j < TN; ++j)
                    acc[i][j] = fmaf(af[i], bf[j], acc[i][j]);
        }
        __syncthreads();
    }

    #pragma unroll
    for (int i = 0; i < TM; ++i) {
        int row = m0 + ty * TM + i;
        #pragma unroll
        for (int j = 0; j < TN; ++j)
            C[(size_t)row * N + n0 + tx * TN + j] = acc[i][j];
    }
}

// ---------------------------------------------------------------------------
// out = act(sum_z part[z] + bias [+ C0]); fixed order -> deterministic.
// ---------------------------------------------------------------------------
template<int S, bool RELU, bool ADDC0>
__global__ void combine_k(const float* __restrict__ bias,
                          const float* __restrict__ C0,
                          float* __restrict__ out, int MN4, int N4) {
    int i = blockIdx.x * blockDim.x + threadIdx.x;
    if (i >= MN4) return;
    const float4* p = (const float4*)g_part;
    float4 v = __ldg(&((const float4*)bias)[i % N4]);
    #pragma unroll
    for (int s = 0; s < S; ++s) {
        float4 q = p[(size_t)s * MN4 + i];
        v.x += q.x; v.y += q.y; v.z += q.z; v.w += q.w;
    }
    if (ADDC0) {
        float4 c = ((const float4*)C0)[i];
        v.x += c.x; v.y += c.y; v.z += c.z; v.w += c.w;
    }
    if (RELU) {
        v.x = fmaxf(v.x, 0.f); v.y = fmaxf(v.y, 0.f);
        v.z = fmaxf(v.z, 0.f); v.w = fmaxf(v.w, 0.f);
    }
    ((float4*)out)[i] = v;
}

// ---------------------------------------------------------------------------
extern "C" void kernel_launch(void* const* d_in, const int* in_sizes, int n_in,
                              void* d_out, int out_size) {
    (void)in_sizes; (void)n_in; (void)out_size;

    const float* T_name        = (const float*)d_in[0];
    const float* T_collab      = (const float*)d_in[1];
    const float* T_track_can   = (const float*)d_in[2];
    const float* T_artist_name = (const float*)d_in[3];
    const float* T_track_uri   = (const float*)d_in[4];
    const float* T_track_name  = (const float*)d_in[5];
    const float* T_dur         = (const float*)d_in[6];
    const float* T_album       = (const float*)d_in[7];
    const float* T_apop        = (const float*)d_in[8];
    const float* T_afol        = (const float*)d_in[9];
    const float* T_tpop        = (const float*)d_in[10];
    const float* T_genres      = (const float*)d_in[11];
    const float* W1 = (const float*)d_in[12];
    const float* b1 = (const float*)d_in[13];
    const float* W2 = (const float*)d_in[14];
    const float* b2 = (const float*)d_in[15];
    const float* W3 = (const float*)d_in[16];
    const float* b3 = (const float*)d_in[17];
    const int* id_name         = (const int*)d_in[18];
    const int* id_collab       = (const int*)d_in[19];
    const int* id_track_can    = (const int*)d_in[20];
    const int* seq_artist_name = (const int*)d_in[21];
    const int* seq_track_uri   = (const int*)d_in[22];
    const int* seq_track_name  = (const int*)d_in[23];
    const int* seq_dur         = (const int*)d_in[24];
    const int* seq_album       = (const int*)d_in[25];
    const int* seq_apop        = (const int*)d_in[26];
    const int* seq_afol        = (const int*)d_in[27];
    const int* seq_tpop        = (const int*)d_in[28];
    const int* seq_genres      = (const int*)d_in[29];

    float *Y0, *H1, *H2;
    cudaGetSymbolAddress((void**)&Y0, g_Y0);
    cudaGetSymbolAddress((void**)&H1, g_H1);
    cudaGetSymbolAddress((void**)&H2, g_H2);

    MegaArgs ma;
    ma.tbl[0] = T_name;        ma.idx[0] = id_name;
    ma.tbl[1] = T_track_can;   ma.idx[1] = id_track_can;
    ma.tbl[2] = T_artist_name; ma.idx[2] = seq_artist_name;
    ma.tbl[3] = T_track_uri;   ma.idx[3] = seq_track_uri;
    ma.tbl[4] = T_track_name;  ma.idx[4] = seq_track_name;
    ma.tbl[5] = T_album;       ma.idx[5] = seq_album;
    ma.tbl[6] = T_genres;      ma.idx[6] = seq_genres;
    ma.W1 = W1;

    // independent small-feature fold (cheap, serial at front)
    precompute_P<<<88, 512>>>(T_collab, T_dur, T_apop, T_afol, T_tpop, W1);
    small_pool<<<NB, 128>>>(id_collab, seq_dur, seq_apop, seq_afol, seq_tpop);

    // fused pooling + GEMM1 (persistent, mblk-major interleaved queue)
    init_mega<<<1, 128>>>();
    mega<<<592, 256>>>(ma);

    // H1 = relu(sum_zc part[zc] + Y0 + b1)
    combine_k<28, true, true><<<(NB * 512 / 4 + 255) / 256, 256>>>(
        b1, Y0, H1, NB * 512 / 4, 512 / 4);

    // layer 2: [1024,512] @ W2; split-K=2 (Kc=256) -> 256 blocks
    gemm_split<32, 64, 2, 4><<<dim3(256 / 64, NB / 32, 2), 256>>>(
        H1, W2, NB, 256, 512, 256);
    combine_k<2, true, false><<<(NB * 256 / 4 + 255) / 256, 256>>>(
        b2, nullptr, H2, NB * 256 / 4, 256 / 4);

    // layer 3: [1024,256] @ W3; split-K=4 (Kc=64) -> 256 blocks
    gemm_split<32, 64, 2, 4><<<dim3(128 / 64, NB / 32, 4), 256>>>(
        H2, W3, NB, 128, 256, 64);
    combine_k<4, false, false><<<(NB * 128 / 4 + 255) / 256, 256>>>(
        b3, nullptr, (float*)d_out, NB * 128 / 4, 128 / 4);
}